// round 9
// baseline (speedup 1.0000x reference)
#include <cuda_runtime.h>
#include <cstdint>

#define NTOK 65536
#define DDIM 2048
#define KEXP 64
#define BM   128
#define KC   32
#define NCHUNK (DDIM / KC)          // 64
#define NSTAGE 3
#define B_STAGE_BYTES 4096          // [ks(2)][nb(8)][64 words] f16-packed
#define SMEM_TOTAL 34816            // max(3*4096, 128*68*4) -- ls overlays B stages
#define LS_STRIDE 68
#define TIE_TAU 2e-3f
#define MAXFIX 8192

// W pre-converted to fp16, FRAGMENT-MAJOR for m16n8k16 B operand:
// word index = (kb*8 + nb)*64 + lane*2 + reg
//   halves (lo,hi of word) = W[n][k0], W[n][k0+1]
//   n = nb*8 + (lane>>2), k0 = kb*16 + (lane&3)*2 + reg*8
__device__ uint32_t g_Wf[128 * 8 * 64];
__device__ int g_cnt;
__device__ int g_rows[MAXFIX];

#define CVT_F16X2(res, f_lo, f_hi) \
    asm("cvt.rn.f16x2.f32 %0, %1, %2;" : "=r"(res) : "f"(f_hi), "f"(f_lo))

__global__ void wprep_kernel(const float* __restrict__ W) {
    int i = blockIdx.x * 256 + threadIdx.x;          // 0 .. 65535
    if (i == 0) g_cnt = 0;                           // reset flag list every launch
    int reg  = i & 1;
    int lane = (i >> 1) & 31;
    int nb   = (i >> 6) & 7;
    int kb   = i >> 9;
    int n  = nb * 8 + (lane >> 2);
    int k0 = kb * 16 + (lane & 3) * 2 + reg * 8;
    float v0 = W[n * DDIM + k0];
    float v1 = W[n * DDIM + k0 + 1];
    uint32_t w;
    CVT_F16X2(w, v0, v1);
    g_Wf[i] = w;
}

#define CP16(dst_u32, src_ptr) \
    asm volatile("cp.async.cg.shared.global [%0], [%1], 16;" :: "r"(dst_u32), "l"(src_ptr))
#define CP_COMMIT() asm volatile("cp.async.commit_group;" ::: "memory")

#define MMA_F16(c, a, b0_, b1_) \
    asm volatile("mma.sync.aligned.m16n8k16.row.col.f32.f16.f16.f32 " \
                 "{%0,%1,%2,%3}, {%4,%5,%6,%7}, {%8,%9}, {%0,%1,%2,%3};" \
                 : "+f"((c)[0]), "+f"((c)[1]), "+f"((c)[2]), "+f"((c)[3]) \
                 : "r"((a)[0]), "r"((a)[1]), "r"((a)[2]), "r"((a)[3]), \
                   "r"(b0_), "r"(b1_))

__global__ __launch_bounds__(256, 3)
void top2gate_tc(const float* __restrict__ x,
                 const float* __restrict__ b,
                 float* __restrict__ out) {
    extern __shared__ char smem[];
    uint32_t sb;
    asm("{ .reg .u64 t; cvta.to.shared.u64 t, %1; cvt.u32.u64 %0, t; }"
        : "=r"(sb) : "l"((const void*)smem));

    __shared__ float s_bias[KEXP];
    __shared__ int   s_i1[BM], s_i2[BM];
    __shared__ float s_q1[BM], s_q2[BM];

    const int tid  = threadIdx.x;
    const int lane = tid & 31;
    const int wid  = tid >> 5;
    const int g    = lane >> 2;       // groupID 0..7
    const int tg   = lane & 3;        // tid-in-group
    const int r0w  = wid * 16;        // warp M-tile base (M16 x N64 per warp)
    const int row0 = blockIdx.x * BM;

    if (tid < KEXP) s_bias[tid] = b[tid];

    float acc[8][4];
    #pragma unroll
    for (int nb = 0; nb < 8; nb++)
        #pragma unroll
        for (int c = 0; c < 4; c++) acc[nb][c] = 0.f;

    // A: direct coalesced LDG.64 of fragments (quad reads one 32B sector)
    // thread base: row = row0 + r0w + g, col = tg*2; second row at +8*DDIM
    const float* aptr = x + (size_t)(row0 + r0w + g) * DDIM + tg * 2;

    // raw fragment loads for chunk t: [rr(2)][ks(2)][h(2)] -> raw[rr*4+ks*2+h]
    auto lda = [&](int t, float2* raw) {
        #pragma unroll
        for (int rr = 0; rr < 2; rr++)
            #pragma unroll
            for (int ks = 0; ks < 2; ks++)
                #pragma unroll
                for (int h = 0; h < 2; h++)
                    raw[rr * 4 + ks * 2 + h] =
                        *(const float2*)(aptr + (size_t)rr * 8 * DDIM + t * KC + ks * 16 + h * 8);
    };
    // cvt raw -> packed f16 fragments aF[ks][0..3]
    auto cvtA = [&](const float2* raw, uint32_t aF[2][4]) {
        #pragma unroll
        for (int ks = 0; ks < 2; ks++) {
            CVT_F16X2(aF[ks][0], raw[0 + ks * 2].x, raw[0 + ks * 2].y);       // row g,   k lo
            CVT_F16X2(aF[ks][1], raw[4 + ks * 2].x, raw[4 + ks * 2].y);       // row g+8, k lo
            CVT_F16X2(aF[ks][2], raw[1 + ks * 2].x, raw[1 + ks * 2].y);       // row g,   k hi
            CVT_F16X2(aF[ks][3], raw[5 + ks * 2].x, raw[5 + ks * 2].y);       // row g+8, k hi
        }
    };

    // B copy for chunk t into stage t % NSTAGE (one CP16 per thread = 4KB)
    auto issueB = [&](int t) {
        uint32_t db = sb + (t % NSTAGE) * B_STAGE_BYTES;
        CP16(db + (uint32_t)tid * 16, (const void*)(g_Wf + t * 1024 + tid * 4));
        CP_COMMIT();
    };

    issueB(0);
    issueB(1);

    uint32_t aF[2][4];
    {
        float2 raw0[8];
        lda(0, raw0);
        cvtA(raw0, aF);
    }

    for (int t = 0; t < NCHUNK; t++) {
        if (t == NCHUNK - 1) {
            asm volatile("cp.async.wait_group 0;" ::: "memory");
        } else {
            asm volatile("cp.async.wait_group 1;" ::: "memory");
        }
        __syncthreads();
        if (t + 2 < NCHUNK) issueB(t + 2);   // stage (t+2)%3: free after sync

        // prefetch next chunk's A into registers (DRAM latency hidden by MMA block)
        float2 rawN[8];
        if (t + 1 < NCHUNK) lda(t + 1, rawN);

        const uint32_t dbB = sb + (t % NSTAGE) * B_STAGE_BYTES;
        #pragma unroll
        for (int ks = 0; ks < 2; ks++) {
            // depth-1 pipelined B loads feeding 8 MMAs
            uint32_t bcur0, bcur1, bnxt0, bnxt1;
            uint32_t ad0 = dbB + (uint32_t)((ks * 512 + lane * 2) * 4);
            asm volatile("ld.shared.v2.b32 {%0,%1}, [%2];"
                         : "=r"(bcur0), "=r"(bcur1) : "r"(ad0));
            #pragma unroll
            for (int nb = 0; nb < 8; nb++) {
                if (nb < 7) {
                    uint32_t ad = dbB + (uint32_t)((ks * 512 + (nb + 1) * 64 + lane * 2) * 4);
                    asm volatile("ld.shared.v2.b32 {%0,%1}, [%2];"
                                 : "=r"(bnxt0), "=r"(bnxt1) : "r"(ad));
                }
                MMA_F16(acc[nb], aF[ks], bcur0, bcur1);
                bcur0 = bnxt0; bcur1 = bnxt1;
            }
        }
        // convert prefetched raw -> aF for next iteration (after MMAs: short raw lifetime)
        if (t + 1 < NCHUNK) cvtA(rawN, aF);
    }
    __syncthreads();

    // ---- epilogue: park logits in smem (overlays B stages) ----
    float* ls = (float*)smem;   // [BM][LS_STRIDE]
    #pragma unroll
    for (int nb = 0; nb < 8; nb++) {
        int r = r0w + g;
        int c = nb * 8 + tg * 2;
        *(float2*)&ls[r * LS_STRIDE + c]       = make_float2(acc[nb][0], acc[nb][1]);
        *(float2*)&ls[(r + 8) * LS_STRIDE + c] = make_float2(acc[nb][2], acc[nb][3]);
    }
    __syncthreads();

    float* out_p = out;
    float* out_e = out + (size_t)NTOK * KEXP;
    float* out_l = out_e + NTOK;

    if (tid < BM) {
        const int row = tid;
        const float* lrow = &ls[row * LS_STRIDE];
        float m1 = -1e30f, m2 = -1e30f, m3 = -1e30f;
        int i1 = 0, i2 = 0;
        #pragma unroll
        for (int c = 0; c < KEXP; c++) {
            float v = lrow[c] + s_bias[c];
            if (v > m1)      { m3 = m2; m2 = m1; i2 = i1; m1 = v; i1 = c; }
            else if (v > m2) { m3 = m2; m2 = v;  i2 = c; }
            else if (v > m3) { m3 = v; }
        }
        // near-tie at top-2/top-3 boundary -> exact fp32 repair
        if (m2 - m3 < TIE_TAU) {
            int slot = atomicAdd(&g_cnt, 1);
            if (slot < MAXFIX) g_rows[slot] = row0 + row;
        }
        float Z = 0.f;
        #pragma unroll
        for (int c = 0; c < KEXP; c++) Z += expf(lrow[c] + s_bias[c] - m1);
        float p1 = 1.0f / Z;
        float p2 = expf(m2 - m1) / Z;
        float denom = p1 + p2 + 1e-9f;
        float q1 = p1 / denom, q2 = p2 / denom;
        float ent = -(q1 * logf(fmaxf(q1, 1e-12f)) + q2 * logf(fmaxf(q2, 1e-12f)));
        s_i1[row] = i1; s_i2[row] = i2; s_q1[row] = q1; s_q2[row] = q2;
        out_e[row0 + row] = ent;
    }
    __syncthreads();

    // coalesced sweep: top2_probs + logits (+bias)
    #pragma unroll
    for (int i = 0; i < 8; i++) {
        int idx = tid + 256 * i;        // 0..2047
        int row = idx >> 4;
        int col = (idx & 15) * 4;
        int i1 = s_i1[row], i2 = s_i2[row];
        float q1 = s_q1[row], q2 = s_q2[row];
        float4 pv;
        pv.x = (col + 0 == i1) ? q1 : ((col + 0 == i2) ? q2 : 0.f);
        pv.y = (col + 1 == i1) ? q1 : ((col + 1 == i2) ? q2 : 0.f);
        pv.z = (col + 2 == i1) ? q1 : ((col + 2 == i2) ? q2 : 0.f);
        pv.w = (col + 3 == i1) ? q1 : ((col + 3 == i2) ? q2 : 0.f);
        float4 lv;
        lv.x = ls[row * LS_STRIDE + col + 0] + s_bias[col + 0];
        lv.y = ls[row * LS_STRIDE + col + 1] + s_bias[col + 1];
        lv.z = ls[row * LS_STRIDE + col + 2] + s_bias[col + 2];
        lv.w = ls[row * LS_STRIDE + col + 3] + s_bias[col + 3];
        size_t gaddr = (size_t)(row0 + row) * KEXP + col;
        *(float4*)&out_p[gaddr] = pv;
        *(float4*)&out_l[gaddr] = lv;
    }
}

// exact-fp32 repair for near-tie rows
__global__ void __launch_bounds__(256, 4)
fix_kernel(const float* __restrict__ x, const float* __restrict__ W,
           const float* __restrict__ b, float* __restrict__ out) {
    __shared__ float sx[DDIM];
    __shared__ float sl[KEXP];
    const int tid = threadIdx.x;
    const int e   = tid >> 2;
    const int p   = tid & 3;
    const int n   = min(g_cnt, MAXFIX);

    float* out_p = out;
    float* out_e = out + (size_t)NTOK * KEXP;
    float* out_l = out_e + NTOK;

    for (int i = blockIdx.x; i < n; i += gridDim.x) {
        const int row = g_rows[i];
        for (int j = tid; j < DDIM; j += 256)
            sx[j] = x[(size_t)row * DDIM + j];
        __syncthreads();

        float s = 0.f;
        const float* wr = W + (size_t)e * DDIM + p;
        #pragma unroll 8
        for (int j = 0; j < DDIM / 4; j++)
            s = fmaf(sx[p + 4 * j], wr[4 * j], s);
        s += __shfl_xor_sync(0xFFFFFFFFu, s, 1);
        s += __shfl_xor_sync(0xFFFFFFFFu, s, 2);
        if (p == 0) sl[e] = s + b[e];
        __syncthreads();

        if (tid < KEXP) {
            float m1 = -1e30f, m2 = -1e30f;
            int i1 = 0, i2 = 0;
            #pragma unroll
            for (int c = 0; c < KEXP; c++) {
                float v = sl[c];
                if (v > m1)      { m2 = m1; i2 = i1; m1 = v; i1 = c; }
                else if (v > m2) { m2 = v;  i2 = c; }
            }
            float Z = 0.f;
            #pragma unroll
            for (int c = 0; c < KEXP; c++) Z += expf(sl[c] - m1);
            float p1 = 1.0f / Z;
            float p2 = expf(m2 - m1) / Z;
            float denom = p1 + p2 + 1e-9f;
            float q1 = p1 / denom, q2 = p2 / denom;
            size_t gr = (size_t)row * KEXP;
            out_l[gr + tid] = sl[tid];
            out_p[gr + tid] = (tid == i1) ? q1 : ((tid == i2) ? q2 : 0.f);
            if (tid == 0)
                out_e[row] = -(q1 * logf(fmaxf(q1, 1e-12f)) +
                               q2 * logf(fmaxf(q2, 1e-12f)));
        }
        __syncthreads();
    }
}

extern "C" void kernel_launch(void* const* d_in, const int* in_sizes, int n_in,
                              void* d_out, int out_size) {
    const float* x = (const float*)d_in[0];
    const float* W = (const float*)d_in[1];
    const float* b = (const float*)d_in[2];
    cudaFuncSetAttribute(top2gate_tc, cudaFuncAttributeMaxDynamicSharedMemorySize, SMEM_TOTAL);
    wprep_kernel<<<256, 256>>>(W);
    top2gate_tc<<<NTOK / BM, 256, SMEM_TOTAL>>>(x, b, (float*)d_out);
    fix_kernel<<<148, 256>>>(x, W, b, (float*)d_out);
}

// round 10
// speedup vs baseline: 1.2407x; 1.2407x over previous
#include <cuda_runtime.h>
#include <cstdint>

#define NTOK 65536
#define DDIM 2048
#define KEXP 64
#define BM   128
#define KC   32
#define NCHUNK (DDIM / KC)          // 64
#define ASTRIDE 36                  // fp32 words per A row (32 data + 4 pad)
#define A_STAGE_BYTES (BM * ASTRIDE * 4)     // 18432
#define NSTAGE 2
#define SM_B_OFF (NSTAGE * A_STAGE_BYTES)    // 36864
#define B_STAGE_BYTES 4096                   // [ks(2)][nb(8)][64 words] f16-packed
#define SMEM_TOTAL (SM_B_OFF + NSTAGE * B_STAGE_BYTES)  // 45056 -> occ 4
#define LS_STRIDE 68
#define TIE_TAU 2e-3f
#define MAXFIX 8192

// W pre-converted to fp16, FRAGMENT-MAJOR for m16n8k16 B operand:
// word index = (kb*8 + nb)*64 + lane*2 + reg
//   halves (lo,hi of word) = W[n][k0], W[n][k0+1]
//   n = nb*8 + (lane>>2), k0 = kb*16 + (lane&3)*2 + reg*8
__device__ uint32_t g_Wf[128 * 8 * 64];
__device__ int g_cnt;
__device__ int g_rows[MAXFIX];

#define CVT_F16X2(res, f_lo, f_hi) \
    asm("cvt.rn.f16x2.f32 %0, %1, %2;" : "=r"(res) : "f"(f_hi), "f"(f_lo))

__global__ void wprep_kernel(const float* __restrict__ W) {
    int i = blockIdx.x * 256 + threadIdx.x;          // 0 .. 65535
    if (i == 0) g_cnt = 0;                           // reset flag list every launch
    int reg  = i & 1;
    int lane = (i >> 1) & 31;
    int nb   = (i >> 6) & 7;
    int kb   = i >> 9;
    int n  = nb * 8 + (lane >> 2);
    int k0 = kb * 16 + (lane & 3) * 2 + reg * 8;
    float v0 = W[n * DDIM + k0];
    float v1 = W[n * DDIM + k0 + 1];
    uint32_t w;
    CVT_F16X2(w, v0, v1);
    g_Wf[i] = w;
}

#define CP16(dst_u32, src_ptr) \
    asm volatile("cp.async.cg.shared.global [%0], [%1], 16;" :: "r"(dst_u32), "l"(src_ptr))
#define CP_COMMIT() asm volatile("cp.async.commit_group;" ::: "memory")

#define MMA_F16(c, a, b0_, b1_) \
    asm volatile("mma.sync.aligned.m16n8k16.row.col.f32.f16.f16.f32 " \
                 "{%0,%1,%2,%3}, {%4,%5,%6,%7}, {%8,%9}, {%0,%1,%2,%3};" \
                 : "+f"((c)[0]), "+f"((c)[1]), "+f"((c)[2]), "+f"((c)[3]) \
                 : "r"((a)[0]), "r"((a)[1]), "r"((a)[2]), "r"((a)[3]), \
                   "r"(b0_), "r"(b1_))

__global__ __launch_bounds__(256, 4)
void top2gate_tc(const float* __restrict__ x,
                 const float* __restrict__ b,
                 float* __restrict__ out) {
    extern __shared__ char smem[];
    uint32_t sb;
    asm("{ .reg .u64 t; cvta.to.shared.u64 t, %1; cvt.u32.u64 %0, t; }"
        : "=r"(sb) : "l"((const void*)smem));

    __shared__ float s_bias[KEXP];
    __shared__ int   s_i1[BM], s_i2[BM];
    __shared__ float s_q1[BM], s_q2[BM];

    const int tid  = threadIdx.x;
    const int lane = tid & 31;
    const int wid  = tid >> 5;
    const int g    = lane >> 2;       // groupID 0..7
    const int tg   = lane & 3;        // tid-in-group
    const int r0w  = wid * 16;        // warp M-tile base (M16 x N64 per warp)
    const int row0 = blockIdx.x * BM;

    if (tid < KEXP) s_bias[tid] = b[tid];

    float acc[8][4];
    #pragma unroll
    for (int nb = 0; nb < 8; nb++)
        #pragma unroll
        for (int c = 0; c < 4; c++) acc[nb][c] = 0.f;

    // issue cp.async for chunk t into stage t & 1 (A raw fp32 rows + B fp16 frags)
    auto issue_chunk = [&](int t) {
        const int st = t & 1;
        const float* xs = x + (size_t)row0 * DDIM + t * KC;
        uint32_t da = sb + st * A_STAGE_BYTES;
        #pragma unroll
        for (int q = 0; q < 4; q++) {
            int idx = tid + 256 * q;          // 0..1023
            int r   = idx >> 3;               // row 0..127
            int seg = idx & 7;                // 16B segment (32 floats/row)
            CP16(da + (uint32_t)(r * ASTRIDE + seg * 4) * 4,
                 xs + (size_t)r * DDIM + seg * 4);
        }
        uint32_t db = sb + SM_B_OFF + st * B_STAGE_BYTES;
        CP16(db + (uint32_t)tid * 16, (const void*)(g_Wf + t * 1024 + tid * 4));
        CP_COMMIT();
    };

    issue_chunk(0);

    for (int t = 0; t < NCHUNK; t++) {
        // stage (t+1)&1 is free: trailing sync of iteration t-1 drained readers
        if (t + 1 < NCHUNK) {
            issue_chunk(t + 1);
            asm volatile("cp.async.wait_group 1;" ::: "memory");   // group(t) done
        } else {
            asm volatile("cp.async.wait_group 0;" ::: "memory");
        }
        __syncthreads();

        const int st = t & 1;
        const float* A = (const float*)(smem + st * A_STAGE_BYTES);
        const uint32_t dbB = sb + SM_B_OFF + st * B_STAGE_BYTES;

        #pragma unroll
        for (int ks = 0; ks < 2; ks++) {
            // A fragments (M16): fp32 pairs -> packed f16x2
            uint32_t aF[4];
            {
                const int r = r0w + g;
                const int c0 = ks * 16 + tg * 2;
                float2 p0 = *(const float2*)&A[r * ASTRIDE + c0];
                float2 p1 = *(const float2*)&A[(r + 8) * ASTRIDE + c0];
                float2 p2 = *(const float2*)&A[r * ASTRIDE + c0 + 8];
                float2 p3 = *(const float2*)&A[(r + 8) * ASTRIDE + c0 + 8];
                CVT_F16X2(aF[0], p0.x, p0.y);
                CVT_F16X2(aF[1], p1.x, p1.y);
                CVT_F16X2(aF[2], p2.x, p2.y);
                CVT_F16X2(aF[3], p3.x, p3.y);
            }
            // 8 MMAs, B loaded inline (warp-level parallelism covers LDS latency)
            #pragma unroll
            for (int nb = 0; nb < 8; nb++) {
                uint32_t b0, b1;
                uint32_t ad = dbB + (uint32_t)((ks * 512 + nb * 64 + lane * 2) * 4);
                asm volatile("ld.shared.v2.b32 {%0,%1}, [%2];"
                             : "=r"(b0), "=r"(b1) : "r"(ad));
                MMA_F16(acc[nb], aF, b0, b1);
            }
        }
        __syncthreads();   // license stage st for overwrite by chunk t+2
    }

    // ---- epilogue: park logits in smem (overlays A stages) ----
    float* ls = (float*)smem;   // [BM][LS_STRIDE]
    #pragma unroll
    for (int nb = 0; nb < 8; nb++) {
        int r = r0w + g;
        int c = nb * 8 + tg * 2;
        *(float2*)&ls[r * LS_STRIDE + c]       = make_float2(acc[nb][0], acc[nb][1]);
        *(float2*)&ls[(r + 8) * LS_STRIDE + c] = make_float2(acc[nb][2], acc[nb][3]);
    }
    __syncthreads();

    float* out_p = out;
    float* out_e = out + (size_t)NTOK * KEXP;
    float* out_l = out_e + NTOK;

    if (tid < BM) {
        const int row = tid;
        const float* lrow = &ls[row * LS_STRIDE];
        float m1 = -1e30f, m2 = -1e30f, m3 = -1e30f;
        int i1 = 0, i2 = 0;
        #pragma unroll
        for (int c = 0; c < KEXP; c++) {
            float v = lrow[c] + s_bias[c];
            if (v > m1)      { m3 = m2; m2 = m1; i2 = i1; m1 = v; i1 = c; }
            else if (v > m2) { m3 = m2; m2 = v;  i2 = c; }
            else if (v > m3) { m3 = v; }
        }
        // near-tie at top-2/top-3 boundary -> exact fp32 repair
        if (m2 - m3 < TIE_TAU) {
            int slot = atomicAdd(&g_cnt, 1);
            if (slot < MAXFIX) g_rows[slot] = row0 + row;
        }
        float Z = 0.f;
        #pragma unroll
        for (int c = 0; c < KEXP; c++) Z += expf(lrow[c] + s_bias[c] - m1);
        float p1 = 1.0f / Z;
        float p2 = expf(m2 - m1) / Z;
        float denom = p1 + p2 + 1e-9f;
        float q1 = p1 / denom, q2 = p2 / denom;
        float ent = -(q1 * logf(fmaxf(q1, 1e-12f)) + q2 * logf(fmaxf(q2, 1e-12f)));
        s_i1[row] = i1; s_i2[row] = i2; s_q1[row] = q1; s_q2[row] = q2;
        out_e[row0 + row] = ent;
    }
    __syncthreads();

    // coalesced sweep: top2_probs + logits (+bias)
    #pragma unroll
    for (int i = 0; i < 8; i++) {
        int idx = tid + 256 * i;        // 0..2047
        int row = idx >> 4;
        int col = (idx & 15) * 4;
        int i1 = s_i1[row], i2 = s_i2[row];
        float q1 = s_q1[row], q2 = s_q2[row];
        float4 pv;
        pv.x = (col + 0 == i1) ? q1 : ((col + 0 == i2) ? q2 : 0.f);
        pv.y = (col + 1 == i1) ? q1 : ((col + 1 == i2) ? q2 : 0.f);
        pv.z = (col + 2 == i1) ? q1 : ((col + 2 == i2) ? q2 : 0.f);
        pv.w = (col + 3 == i1) ? q1 : ((col + 3 == i2) ? q2 : 0.f);
        float4 lv;
        lv.x = ls[row * LS_STRIDE + col + 0] + s_bias[col + 0];
        lv.y = ls[row * LS_STRIDE + col + 1] + s_bias[col + 1];
        lv.z = ls[row * LS_STRIDE + col + 2] + s_bias[col + 2];
        lv.w = ls[row * LS_STRIDE + col + 3] + s_bias[col + 3];
        size_t gaddr = (size_t)(row0 + row) * KEXP + col;
        *(float4*)&out_p[gaddr] = pv;
        *(float4*)&out_l[gaddr] = lv;
    }
}

// exact-fp32 repair for near-tie rows
__global__ void __launch_bounds__(256, 4)
fix_kernel(const float* __restrict__ x, const float* __restrict__ W,
           const float* __restrict__ b, float* __restrict__ out) {
    __shared__ float sx[DDIM];
    __shared__ float sl[KEXP];
    const int tid = threadIdx.x;
    const int e   = tid >> 2;
    const int p   = tid & 3;
    const int n   = min(g_cnt, MAXFIX);

    float* out_p = out;
    float* out_e = out + (size_t)NTOK * KEXP;
    float* out_l = out_e + NTOK;

    for (int i = blockIdx.x; i < n; i += gridDim.x) {
        const int row = g_rows[i];
        for (int j = tid; j < DDIM; j += 256)
            sx[j] = x[(size_t)row * DDIM + j];
        __syncthreads();

        float s = 0.f;
        const float* wr = W + (size_t)e * DDIM + p;
        #pragma unroll 8
        for (int j = 0; j < DDIM / 4; j++)
            s = fmaf(sx[p + 4 * j], wr[4 * j], s);
        s += __shfl_xor_sync(0xFFFFFFFFu, s, 1);
        s += __shfl_xor_sync(0xFFFFFFFFu, s, 2);
        if (p == 0) sl[e] = s + b[e];
        __syncthreads();

        if (tid < KEXP) {
            float m1 = -1e30f, m2 = -1e30f;
            int i1 = 0, i2 = 0;
            #pragma unroll
            for (int c = 0; c < KEXP; c++) {
                float v = sl[c];
                if (v > m1)      { m2 = m1; i2 = i1; m1 = v; i1 = c; }
                else if (v > m2) { m2 = v;  i2 = c; }
            }
            float Z = 0.f;
            #pragma unroll
            for (int c = 0; c < KEXP; c++) Z += expf(sl[c] - m1);
            float p1 = 1.0f / Z;
            float p2 = expf(m2 - m1) / Z;
            float denom = p1 + p2 + 1e-9f;
            float q1 = p1 / denom, q2 = p2 / denom;
            size_t gr = (size_t)row * KEXP;
            out_l[gr + tid] = sl[tid];
            out_p[gr + tid] = (tid == i1) ? q1 : ((tid == i2) ? q2 : 0.f);
            if (tid == 0)
                out_e[row] = -(q1 * logf(fmaxf(q1, 1e-12f)) +
                               q2 * logf(fmaxf(q2, 1e-12f)));
        }
        __syncthreads();
    }
}

extern "C" void kernel_launch(void* const* d_in, const int* in_sizes, int n_in,
                              void* d_out, int out_size) {
    const float* x = (const float*)d_in[0];
    const float* W = (const float*)d_in[1];
    const float* b = (const float*)d_in[2];
    cudaFuncSetAttribute(top2gate_tc, cudaFuncAttributeMaxDynamicSharedMemorySize, SMEM_TOTAL);
    wprep_kernel<<<256, 256>>>(W);
    top2gate_tc<<<NTOK / BM, 256, SMEM_TOTAL>>>(x, b, (float*)d_out);
    fix_kernel<<<148, 256>>>(x, W, b, (float*)d_out);
}